// round 4
// baseline (speedup 1.0000x reference)
#include <cuda_runtime.h>

// CostVolume: out[b, dy*9+dx, y, x] = leaky( mean_c( c1[b,c,y,x] * warped[b,c,y+dy-4,x+dx-4] ) )
// B=8, C=192, H=128, W=160, 81 offsets.
// Round 4: 4 x-pixels per thread (LDS.128), dy split in 5 groups of 2,
// 72 reg accumulators, vectorized all-or-nothing halo staging, fma-pipe bound.

#define SR 4
#define C_TOTAL 192
#define H_TOTAL 128
#define W_TOTAL 160
#define B_TOTAL 8

#define TW 32        // tile width
#define TH 16        // tile height
#define NTHREADS 128 // 8 x-groups * 16 rows
#define CC 8         // channels per staged chunk
#define NGROUP 5     // dy groups of 2: {0,1}..{8,9(discarded)}
#define HH 17        // halo rows per group: TH + 2 - 1
#define HWPAD 48     // halo cols padded (44 used)

__global__ __launch_bounds__(NTHREADS, 4)
void costvol_kernel(const float* __restrict__ c1,
                    const float* __restrict__ warped,
                    const float* __restrict__ alpha,
                    float* __restrict__ out) {
    __shared__ __align__(16) float s_c1[CC][TH][TW];    // 16 KB
    __shared__ __align__(16) float s_w[CC][HH][HWPAD];  // 26.1 KB

    const int tid = threadIdx.x;
    const int xp  = tid & 7;           // x-group
    const int yp  = tid >> 3;          // pixel row 0..15
    const int tx0 = xp * 4;
    const int gid = blockIdx.x % NGROUP;
    const int x0  = (blockIdx.x / NGROUP) * TW;
    const int y0  = blockIdx.y * TH;
    const int b   = blockIdx.z;
    const int dyb = gid * 2;

    const float av = alpha[0];

    float acc[2][9][4];
    #pragma unroll
    for (int t = 0; t < 2; t++)
        #pragma unroll
        for (int d = 0; d < 9; d++)
            #pragma unroll
            for (int p = 0; p < 4; p++) acc[t][d][p] = 0.f;

    const size_t plane = (size_t)H_TOTAL * W_TOTAL;
    const float* c1b = c1     + (size_t)b * C_TOTAL * plane;
    const float* wb  = warped + (size_t)b * C_TOTAL * plane;

    #pragma unroll 1
    for (int cc = 0; cc < C_TOTAL; cc += CC) {
        // ---- stage c1: CC*16*32 = 1024 float4, 8 per thread, coalesced ----
        #pragma unroll
        for (int i = 0; i < 8; i++) {
            int idx = tid + i * NTHREADS;
            int c   = idx >> 7;
            int rem = idx & 127;
            int yy  = rem >> 3;
            int xx  = (rem & 7) * 4;
            *(float4*)&s_c1[c][yy][xx] =
                *(const float4*)(c1b + (size_t)(cc + c) * plane
                                 + (size_t)(y0 + yy) * W_TOTAL + (x0 + xx));
        }
        // ---- stage warped halo: CC*17 rows * 12 float4 slots ----
        // slot k covers gx = x0-4+4k .. +3: entirely in [0,160) or entirely out.
        #pragma unroll 1
        for (int j = tid; j < CC * HH * 12; j += NTHREADS) {
            int c   = j / (HH * 12);
            int rem = j - c * (HH * 12);
            int r   = rem / 12;
            int k   = rem - r * 12;
            int gy  = y0 + dyb - SR + r;
            int gx  = x0 - SR + k * 4;
            float4 v = make_float4(0.f, 0.f, 0.f, 0.f);
            if ((unsigned)gy < (unsigned)H_TOTAL && (unsigned)gx <= (unsigned)(W_TOTAL - 4))
                v = *(const float4*)(wb + (size_t)(cc + c) * plane
                                     + (size_t)gy * W_TOTAL + gx);
            *(float4*)&s_w[c][r][k * 4] = v;
        }
        __syncthreads();

        // ---- accumulate: 7 LDS.128 feed 72 FFMA per channel ----
        #pragma unroll 1
        for (int c = 0; c < CC; c++) {
            const float4 a = *(const float4*)&s_c1[c][yp][tx0];
            #pragma unroll
            for (int t = 0; t < 2; t++) {
                const float4* wr = (const float4*)&s_w[c][yp + t][tx0];
                float4 w0 = wr[0], w1 = wr[1], w2 = wr[2];
                float w[12] = {w0.x, w0.y, w0.z, w0.w,
                               w1.x, w1.y, w1.z, w1.w,
                               w2.x, w2.y, w2.z, w2.w};
                #pragma unroll
                for (int dx = 0; dx < 9; dx++) {
                    acc[t][dx][0] = fmaf(a.x, w[dx + 0], acc[t][dx][0]);
                    acc[t][dx][1] = fmaf(a.y, w[dx + 1], acc[t][dx][1]);
                    acc[t][dx][2] = fmaf(a.z, w[dx + 2], acc[t][dx][2]);
                    acc[t][dx][3] = fmaf(a.w, w[dx + 3], acc[t][dx][3]);
                }
            }
        }
        __syncthreads();
    }

    // ---- epilogue: mean, leaky-relu, ST.128 ----
    const float inv = 1.0f / (float)C_TOTAL;
    #pragma unroll
    for (int t = 0; t < 2; t++) {
        int dy = dyb + t;
        if (dy > 2 * SR) continue;   // group 4 discards dy=9
        #pragma unroll
        for (int dx = 0; dx < 9; dx++) {
            float4 v;
            float r0 = acc[t][dx][0] * inv;
            float r1 = acc[t][dx][1] * inv;
            float r2 = acc[t][dx][2] * inv;
            float r3 = acc[t][dx][3] * inv;
            v.x = (r0 >= 0.f) ? r0 : av * r0;
            v.y = (r1 >= 0.f) ? r1 : av * r1;
            v.z = (r2 >= 0.f) ? r2 : av * r2;
            v.w = (r3 >= 0.f) ? r3 : av * r3;
            *(float4*)(out + (size_t)b * 81 * plane + (size_t)(dy * 9 + dx) * plane
                       + (size_t)(y0 + yp) * W_TOTAL + (x0 + tx0)) = v;
        }
    }
}

extern "C" void kernel_launch(void* const* d_in, const int* in_sizes, int n_in,
                              void* d_out, int out_size) {
    const float* c1     = (const float*)d_in[0];
    const float* warped = (const float*)d_in[1];
    const float* alpha  = (const float*)d_in[2];
    float* out          = (float*)d_out;

    dim3 grid(NGROUP * (W_TOTAL / TW), H_TOTAL / TH, B_TOTAL);  // (25, 8, 8)
    dim3 block(NTHREADS);
    costvol_kernel<<<grid, block>>>(c1, warped, alpha, out);
}

// round 5
// speedup vs baseline: 1.6911x; 1.6911x over previous
#include <cuda_runtime.h>
#include <cstdint>

// CostVolume: out[b, dy*9+dx, y, x] = leaky( mean_c( c1[b,c,y,x] * warped[b,c,y+dy-4,x+dx-4] ) )
// B=8, C=192, H=128, W=160, 81 offsets.
// Round 5: 1 dy per block (9 groups, zero waste), 8 x-pixels/thread, packed
// fma.rn.f32x2 accumulators (36 FFMA2/channel), cp.async double-buffered staging
// with fully hoisted address math, conflict-free padded smem.

#define SR 4
#define C_TOTAL 192
#define H_TOTAL 128
#define W_TOTAL 160
#define B_TOTAL 8

#define TW 32
#define TH 32
#define NTHREADS 128      // 4 x-groups * 32 rows
#define CC 2              // channels per chunk
#define NCHUNK (C_TOTAL / CC)   // 96
#define NGROUP 9          // one dy per block
#define C1PAD 36          // padded c1 row (floats)
#define WPAD 44           // padded halo row (floats); 40 used

#define FMA2(d, a, b) \
    asm volatile("fma.rn.f32x2 %0, %1, %2, %0;" : "+l"(d) : "l"(a), "l"(b))
#define PACK2(d, lo, hi) \
    asm volatile("mov.b64 %0, {%1, %2};" : "=l"(d) : "f"(lo), "f"(hi))
#define UNPACK2(lo, hi, v) \
    asm volatile("mov.b64 {%0, %1}, %2;" : "=f"(lo), "=f"(hi) : "l"(v))
#define CP16(smem_u32, gptr, sz) \
    asm volatile("cp.async.cg.shared.global [%0], [%1], 16, %2;" \
                 :: "r"(smem_u32), "l"(gptr), "r"(sz))
#define CP_COMMIT() asm volatile("cp.async.commit_group;")
#define CP_WAIT(n)  asm volatile("cp.async.wait_group %0;" :: "n"(n))

__device__ __forceinline__ uint32_t smem_u32(const void* p) {
    uint32_t a;
    asm("{ .reg .u64 t; cvta.to.shared.u64 t, %1; cvt.u32.u64 %0, t; }" : "=r"(a) : "l"(p));
    return a;
}

__global__ __launch_bounds__(NTHREADS, 4)
void costvol_kernel(const float* __restrict__ c1,
                    const float* __restrict__ warped,
                    const float* __restrict__ alpha,
                    float* __restrict__ out) {
    __shared__ __align__(16) float s_c1[2][CC][TH][C1PAD];  // 2 x 9 KB
    __shared__ __align__(16) float s_w[2][CC][TH][WPAD];    // 2 x 11 KB

    const int tid = threadIdx.x;
    const int xg  = tid & 3;            // x-group 0..3
    const int ty  = tid >> 2;           // pixel row 0..31
    const int tx0 = xg * 8;
    const int dy  = blockIdx.x % NGROUP;
    const int x0  = (blockIdx.x / NGROUP) * TW;
    const int y0  = blockIdx.y * TH;
    const int b   = blockIdx.z;

    const size_t plane = (size_t)H_TOTAL * W_TOTAL;
    const float* c1b = c1     + (size_t)b * C_TOTAL * plane;
    const float* wb  = warped + (size_t)b * C_TOTAL * plane;
    const float  av  = alpha[0];

    // ---- hoisted staging geometry (constant across chunks) ----
    // c1: 512 float4 per chunk, 4 per thread
    const float* c1src[4];
    uint32_t     c1dst[4];
    {
        uint32_t base = smem_u32(&s_c1[0][0][0][0]);
        #pragma unroll
        for (int i = 0; i < 4; i++) {
            int idx = tid + i * NTHREADS;      // 0..511
            int c   = idx >> 8;                // 256 float4 per channel
            int rem = idx & 255;
            int yy  = rem >> 3;
            int xx  = (rem & 7) * 4;
            c1src[i] = c1b + (size_t)c * plane + (size_t)(y0 + yy) * W_TOTAL + (x0 + xx);
            c1dst[i] = base + ((c * TH + yy) * C1PAD + xx) * 4;
        }
    }
    // halo: CC*32 rows * 10 float4 slots = 640, 5 per thread
    const float* wsrc[5];
    uint32_t     wdst[5];
    int          wsz[5];
    {
        uint32_t base = smem_u32(&s_w[0][0][0][0]);
        #pragma unroll
        for (int i = 0; i < 5; i++) {
            int j   = tid + i * NTHREADS;      // 0..639
            int c   = j / 320;                 // 320 slots per channel
            int rem = j - c * 320;
            int r   = rem / 10;
            int k   = rem - r * 10;
            int gy  = y0 + dy - SR + r;
            int gx  = x0 - SR + 4 * k;
            bool ok = ((unsigned)gy < (unsigned)H_TOTAL) &&
                      ((unsigned)gx <= (unsigned)(W_TOTAL - 4));
            wsrc[i] = ok ? (wb + (size_t)c * plane + (size_t)gy * W_TOTAL + gx) : wb;
            wsz[i]  = ok ? 16 : 0;
            wdst[i] = base + ((c * TH + r) * WPAD + 4 * k) * 4;
        }
    }
    const uint32_t C1BUF = sizeof(s_c1) / 2;
    const uint32_t WBUF  = sizeof(s_w) / 2;
    const size_t   CHSTEP = (size_t)CC * plane;

    // ---- accumulators: 9 dx x 4 pixel-pairs, packed f32x2 ----
    unsigned long long acc[9][4];
    #pragma unroll
    for (int d = 0; d < 9; d++)
        #pragma unroll
        for (int p = 0; p < 4; p++) acc[d][p] = 0ull;

    // ---- prologue: stage chunk 0 into buffer 0 ----
    {
        #pragma unroll
        for (int i = 0; i < 4; i++) CP16(c1dst[i], c1src[i], 16);
        #pragma unroll
        for (int i = 0; i < 5; i++) CP16(wdst[i], wsrc[i], wsz[i]);
        CP_COMMIT();
    }

    #pragma unroll 1
    for (int ch = 0; ch < NCHUNK; ch++) {
        const int cur = ch & 1;
        if (ch + 1 < NCHUNK) {
            const size_t goff = (size_t)(ch + 1) * CHSTEP;
            const uint32_t bc = (ch + 1) & 1 ? C1BUF : 0;
            const uint32_t bw = (ch + 1) & 1 ? WBUF : 0;
            #pragma unroll
            for (int i = 0; i < 4; i++) CP16(c1dst[i] + bc, c1src[i] + goff, 16);
            #pragma unroll
            for (int i = 0; i < 5; i++) CP16(wdst[i] + bw, wsrc[i] + goff, wsz[i]);
            CP_COMMIT();
            CP_WAIT(1);
        } else {
            CP_WAIT(0);
        }
        __syncthreads();

        #pragma unroll
        for (int c = 0; c < CC; c++) {
            const float4 a01 = *(const float4*)&s_c1[cur][c][ty][tx0];
            const float4 a23 = *(const float4*)&s_c1[cur][c][ty][tx0 + 4];
            const float4 w0  = *(const float4*)&s_w[cur][c][ty][tx0];
            const float4 w1  = *(const float4*)&s_w[cur][c][ty][tx0 + 4];
            const float4 w2  = *(const float4*)&s_w[cur][c][ty][tx0 + 8];
            const float4 w3  = *(const float4*)&s_w[cur][c][ty][tx0 + 12];
            const float w[16] = {w0.x, w0.y, w0.z, w0.w, w1.x, w1.y, w1.z, w1.w,
                                 w2.x, w2.y, w2.z, w2.w, w3.x, w3.y, w3.z, w3.w};
            unsigned long long pa[4];
            PACK2(pa[0], a01.x, a01.y);
            PACK2(pa[1], a01.z, a01.w);
            PACK2(pa[2], a23.x, a23.y);
            PACK2(pa[3], a23.z, a23.w);
            #pragma unroll
            for (int d = 0; d < 15; d++) {
                unsigned long long wp;
                PACK2(wp, w[d], w[d + 1]);
                #pragma unroll
                for (int p = 0; p < 4; p++) {
                    int dx = d - 2 * p;
                    if (dx >= 0 && dx < 9) FMA2(acc[dx][p], pa[p], wp);
                }
            }
        }
        __syncthreads();
    }

    // ---- epilogue: mean, leaky-relu, 2x ST.128 per dx ----
    const float inv = 1.0f / (float)C_TOTAL;
    float* ob = out + (size_t)b * 81 * plane
                    + (size_t)(y0 + ty) * W_TOTAL + (x0 + tx0);
    #pragma unroll
    for (int dx = 0; dx < 9; dx++) {
        float r[8];
        #pragma unroll
        for (int p = 0; p < 4; p++) {
            float lo, hi;
            UNPACK2(lo, hi, acc[dx][p]);
            lo *= inv; hi *= inv;
            r[2 * p]     = (lo >= 0.f) ? lo : av * lo;
            r[2 * p + 1] = (hi >= 0.f) ? hi : av * hi;
        }
        float* o = ob + (size_t)(dy * 9 + dx) * plane;
        *(float4*)(o)     = make_float4(r[0], r[1], r[2], r[3]);
        *(float4*)(o + 4) = make_float4(r[4], r[5], r[6], r[7]);
    }
}

extern "C" void kernel_launch(void* const* d_in, const int* in_sizes, int n_in,
                              void* d_out, int out_size) {
    const float* c1     = (const float*)d_in[0];
    const float* warped = (const float*)d_in[1];
    const float* alpha  = (const float*)d_in[2];
    float* out          = (float*)d_out;

    cudaFuncSetAttribute(costvol_kernel,
                         cudaFuncAttributePreferredSharedMemoryCarveout, 100);

    dim3 grid(NGROUP * (W_TOTAL / TW), H_TOTAL / TH, B_TOTAL);  // (45, 4, 8) = 1440
    dim3 block(NTHREADS);
    costvol_kernel<<<grid, block>>>(c1, warped, alpha, out);
}

// round 6
// speedup vs baseline: 2.4863x; 1.4702x over previous
#include <cuda_runtime.h>
#include <cstdint>

// CostVolume: out[b, dy*9+dx, y, x] = leaky( mean_c( c1[b,c,y,x] * warped[b,c,y+dy-4,x+dx-4] ) )
// B=8, C=192, H=128, W=160, 81 offsets.
// Round 6: one block = 32x4 tile x ALL 9 dy (warp w <-> dy=w). Halo+c1 staged once
// per chunk for all 81 offsets (L2 traffic /9). 4 px/thread, packed fma.rn.f32x2,
// cp.async double-buffered, hoisted staging geometry.

#define SR 4
#define C_TOTAL 192
#define H_TOTAL 128
#define W_TOTAL 160
#define B_TOTAL 8

#define TW 32
#define TH 4
#define NWARP 9
#define NTHREADS (NWARP * 32)     // 288
#define CC 4                      // channels per chunk
#define NCHUNK (C_TOTAL / CC)     // 48
#define HH 12                     // halo rows: TH + 2*SR
#define WPAD 48                   // halo row padded floats (40 used)

#define C1_SLOTS (CC * TH * 8)        // float4 slots per chunk: 128
#define W_SLOTS  (CC * HH * 10)       // 480
#define TOT_SLOTS (C1_SLOTS + W_SLOTS) // 608

#define FMA2(d, a, b) \
    asm volatile("fma.rn.f32x2 %0, %1, %2, %0;" : "+l"(d) : "l"(a), "l"(b))
#define PACK2(d, lo, hi) \
    asm volatile("mov.b64 %0, {%1, %2};" : "=l"(d) : "f"(lo), "f"(hi))
#define UNPACK2(lo, hi, v) \
    asm volatile("mov.b64 {%0, %1}, %2;" : "=f"(lo), "=f"(hi) : "l"(v))
#define CP16(smem_a, gptr, sz) \
    asm volatile("cp.async.cg.shared.global [%0], [%1], 16, %2;" \
                 :: "r"(smem_a), "l"(gptr), "r"(sz))
#define CP_COMMIT() asm volatile("cp.async.commit_group;")
#define CP_WAIT(n)  asm volatile("cp.async.wait_group %0;" :: "n"(n))

__device__ __forceinline__ uint32_t smem_u32(const void* p) {
    uint32_t a;
    asm("{ .reg .u64 t; cvta.to.shared.u64 t, %1; cvt.u32.u64 %0, t; }" : "=r"(a) : "l"(p));
    return a;
}

__global__ __launch_bounds__(NTHREADS, 2)
void costvol_kernel(const float* __restrict__ c1,
                    const float* __restrict__ warped,
                    const float* __restrict__ alpha,
                    float* __restrict__ out) {
    __shared__ __align__(16) float s_c1[2][CC][TH][TW];    // 2 x 2 KB
    __shared__ __align__(16) float s_w[2][CC][HH][WPAD];   // 2 x 9 KB

    const int tid  = threadIdx.x;
    const int lane = tid & 31;
    const int dy   = tid >> 5;          // warp id == dy (0..8)
    const int xg   = lane & 7;
    const int row  = lane >> 3;         // pixel row in tile (0..3)
    const int tx0  = xg * 4;
    const int x0   = blockIdx.x * TW;
    const int y0   = blockIdx.y * TH;
    const int b    = blockIdx.z;

    const size_t plane = (size_t)H_TOTAL * W_TOTAL;
    const float* c1b = c1     + (size_t)b * C_TOTAL * plane;
    const float* wb  = warped + (size_t)b * C_TOTAL * plane;
    const float  av  = alpha[0];

    // ---- hoisted staging geometry: up to 3 (src, dst, size) per thread ----
    const float* src[3];
    uint32_t     dst[3];
    int          sz[3];
    {
        const uint32_t base_c1 = smem_u32(&s_c1[0][0][0][0]);
        const uint32_t base_w  = smem_u32(&s_w[0][0][0][0]);
        #pragma unroll
        for (int i = 0; i < 3; i++) {
            int j = tid + i * NTHREADS;
            if (j < C1_SLOTS) {
                int c   = j >> 5;             // 32 slots per channel
                int rem = j & 31;
                int r   = rem >> 3;
                int xx  = (rem & 7) * 4;
                src[i] = c1b + (size_t)c * plane + (size_t)(y0 + r) * W_TOTAL + (x0 + xx);
                dst[i] = base_c1 + (uint32_t)(((c * TH + r) * TW + xx) * 4);
                sz[i]  = 16;
            } else if (j < TOT_SLOTS) {
                int h   = j - C1_SLOTS;
                int c   = h / (HH * 10);
                int rem = h - c * (HH * 10);
                int r   = rem / 10;
                int k   = rem - r * 10;
                int gy  = y0 + r - SR;
                int gx  = x0 - SR + 4 * k;
                bool ok = ((unsigned)gy < (unsigned)H_TOTAL) &&
                          ((unsigned)gx <= (unsigned)(W_TOTAL - 4));
                src[i] = ok ? (wb + (size_t)c * plane + (size_t)gy * W_TOTAL + gx) : wb;
                dst[i] = base_w + (uint32_t)(((c * HH + r) * WPAD + 4 * k) * 4);
                sz[i]  = ok ? 16 : 0;
            } else {
                src[i] = wb;  dst[i] = base_w;  sz[i] = -1;   // inactive
            }
        }
    }
    const uint32_t C1BUF = sizeof(s_c1) / 2;
    const uint32_t WBUF  = sizeof(s_w) / 2;
    const size_t   CHSTEP = (size_t)CC * plane;

    // dst offset for buffer 1 per slot (c1 vs halo have different buffer sizes)
    uint32_t bufoff[3];
    #pragma unroll
    for (int i = 0; i < 3; i++)
        bufoff[i] = (tid + i * NTHREADS < C1_SLOTS) ? C1BUF : WBUF;

    // ---- accumulators: 9 dx x 2 packed pixel-pairs ----
    unsigned long long acc[9][2];
    #pragma unroll
    for (int d = 0; d < 9; d++) { acc[d][0] = 0ull; acc[d][1] = 0ull; }

    // ---- prologue: chunk 0 -> buffer 0 ----
    #pragma unroll
    for (int i = 0; i < 3; i++)
        if (sz[i] >= 0) CP16(dst[i], src[i], sz[i]);
    CP_COMMIT();

    #pragma unroll 1
    for (int ch = 0; ch < NCHUNK; ch++) {
        const int cur = ch & 1;
        if (ch + 1 < NCHUNK) {
            const size_t  goff = (size_t)(ch + 1) * CHSTEP;
            const uint32_t nb  = (ch + 1) & 1;
            #pragma unroll
            for (int i = 0; i < 3; i++)
                if (sz[i] >= 0) CP16(dst[i] + nb * bufoff[i], src[i] + goff, sz[i]);
            CP_COMMIT();
            CP_WAIT(1);
        } else {
            CP_WAIT(0);
        }
        __syncthreads();

        #pragma unroll
        for (int c = 0; c < CC; c++) {
            const float4 a  = *(const float4*)&s_c1[cur][c][row][tx0];
            const float4 w0 = *(const float4*)&s_w[cur][c][row + dy][tx0];
            const float4 w1 = *(const float4*)&s_w[cur][c][row + dy][tx0 + 4];
            const float4 w2 = *(const float4*)&s_w[cur][c][row + dy][tx0 + 8];
            unsigned long long pa0, pa1;
            PACK2(pa0, a.x, a.y);
            PACK2(pa1, a.z, a.w);
            const float wf[12] = {w0.x, w0.y, w0.z, w0.w, w1.x, w1.y, w1.z, w1.w,
                                  w2.x, w2.y, w2.z, w2.w};
            unsigned long long wp[11];
            #pragma unroll
            for (int d = 0; d < 11; d++) PACK2(wp[d], wf[d], wf[d + 1]);
            #pragma unroll
            for (int dx = 0; dx < 9; dx++) {
                FMA2(acc[dx][0], pa0, wp[dx]);
                FMA2(acc[dx][1], pa1, wp[dx + 2]);
            }
        }
        __syncthreads();
    }

    // ---- epilogue: mean, leaky-relu, one ST.128 per dx ----
    const float inv = 1.0f / (float)C_TOTAL;
    float* ob = out + (size_t)b * 81 * plane + (size_t)(dy * 9) * plane
                    + (size_t)(y0 + row) * W_TOTAL + (x0 + tx0);
    #pragma unroll
    for (int dx = 0; dx < 9; dx++) {
        float r0, r1, r2, r3;
        UNPACK2(r0, r1, acc[dx][0]);
        UNPACK2(r2, r3, acc[dx][1]);
        r0 *= inv; r1 *= inv; r2 *= inv; r3 *= inv;
        float4 v;
        v.x = (r0 >= 0.f) ? r0 : av * r0;
        v.y = (r1 >= 0.f) ? r1 : av * r1;
        v.z = (r2 >= 0.f) ? r2 : av * r2;
        v.w = (r3 >= 0.f) ? r3 : av * r3;
        *(float4*)(ob + (size_t)dx * plane) = v;
    }
}

extern "C" void kernel_launch(void* const* d_in, const int* in_sizes, int n_in,
                              void* d_out, int out_size) {
    const float* c1     = (const float*)d_in[0];
    const float* warped = (const float*)d_in[1];
    const float* alpha  = (const float*)d_in[2];
    float* out          = (float*)d_out;

    cudaFuncSetAttribute(costvol_kernel,
                         cudaFuncAttributePreferredSharedMemoryCarveout, 100);

    dim3 grid(W_TOTAL / TW, H_TOTAL / TH, B_TOTAL);   // (5, 32, 8) = 1280 blocks
    dim3 block(NTHREADS);                              // 288 = 9 warps
    costvol_kernel<<<grid, block>>>(c1, warped, alpha, out);
}

// round 7
// speedup vs baseline: 2.6360x; 1.0602x over previous
#include <cuda_runtime.h>
#include <cstdint>

// CostVolume: out[b, dy*9+dx, y, x] = leaky( mean_c( c1[b,c,y,x] * warped[b,c,y+dy-4,x+dx-4] ) )
// B=8, C=192, H=128, W=160, 81 offsets.
// Round 7: all-FFMA2 inner loop. Even dx via aligned pairs; odd dx via reversed
// multiplier pairs (rev ⊗ aligned pair = two wanted odd-dx cross terms).
// No per-pair packing movs. Warp w == dy, staged once per chunk, cp.async ping-pong.

#define SR 4
#define C_TOTAL 192
#define H_TOTAL 128
#define W_TOTAL 160
#define B_TOTAL 8

#define TW 32
#define TH 4
#define NWARP 9
#define NTHREADS (NWARP * 32)     // 288
#define CC 4
#define NCHUNK (C_TOTAL / CC)     // 48
#define HH 12
#define WPAD 48

#define C1_SLOTS (CC * TH * 8)         // 128
#define W_SLOTS  (CC * HH * 10)        // 480
#define TOT_SLOTS (C1_SLOTS + W_SLOTS) // 608

#define FMA2(d, a, b) \
    asm volatile("fma.rn.f32x2 %0, %1, %2, %0;" : "+l"(d) : "l"(a), "l"(b))
#define PACK2(d, lo, hi) \
    asm volatile("mov.b64 %0, {%1, %2};" : "=l"(d) : "f"(lo), "f"(hi))
#define UNPACK2(lo, hi, v) \
    asm volatile("mov.b64 {%0, %1}, %2;" : "=f"(lo), "=f"(hi) : "l"(v))
#define CP16(smem_a, gptr, sz) \
    asm volatile("cp.async.cg.shared.global [%0], [%1], 16, %2;" \
                 :: "r"(smem_a), "l"(gptr), "r"(sz))
#define CP_COMMIT() asm volatile("cp.async.commit_group;")
#define CP_WAIT(n)  asm volatile("cp.async.wait_group %0;" :: "n"(n))

__device__ __forceinline__ uint32_t smem_u32(const void* p) {
    uint32_t a;
    asm("{ .reg .u64 t; cvta.to.shared.u64 t, %1; cvt.u32.u64 %0, t; }" : "=r"(a) : "l"(p));
    return a;
}

__global__ __launch_bounds__(NTHREADS, 2)
void costvol_kernel(const float* __restrict__ c1,
                    const float* __restrict__ warped,
                    const float* __restrict__ alpha,
                    float* __restrict__ out) {
    __shared__ __align__(16) float s_c1[2][CC][TH][TW];    // 4 KB
    __shared__ __align__(16) float s_w[2][CC][HH][WPAD];   // 18 KB

    const int tid  = threadIdx.x;
    const int lane = tid & 31;
    const int dy   = tid >> 5;          // warp id == dy
    const int xg   = lane & 7;
    const int row  = lane >> 3;
    const int tx0  = xg * 4;
    const int x0   = blockIdx.x * TW;
    const int y0   = blockIdx.y * TH;
    const int b    = blockIdx.z;

    const size_t plane = (size_t)H_TOTAL * W_TOTAL;
    const float* c1b = c1     + (size_t)b * C_TOTAL * plane;
    const float* wb  = warped + (size_t)b * C_TOTAL * plane;
    const float  av  = alpha[0];

    // ---- hoisted staging geometry ----
    const float* src[3];
    uint32_t     dst[3];
    int          sz[3];
    uint32_t     bufoff[3];
    {
        const uint32_t base_c1 = smem_u32(&s_c1[0][0][0][0]);
        const uint32_t base_w  = smem_u32(&s_w[0][0][0][0]);
        #pragma unroll
        for (int i = 0; i < 3; i++) {
            int j = tid + i * NTHREADS;
            if (j < C1_SLOTS) {
                int c   = j >> 5;
                int rem = j & 31;
                int r   = rem >> 3;
                int xx  = (rem & 7) * 4;
                src[i] = c1b + (size_t)c * plane + (size_t)(y0 + r) * W_TOTAL + (x0 + xx);
                dst[i] = base_c1 + (uint32_t)(((c * TH + r) * TW + xx) * 4);
                sz[i]  = 16;
                bufoff[i] = sizeof(s_c1) / 2;
            } else if (j < TOT_SLOTS) {
                int h   = j - C1_SLOTS;
                int c   = h / (HH * 10);
                int rem = h - c * (HH * 10);
                int r   = rem / 10;
                int k   = rem - r * 10;
                int gy  = y0 + r - SR;
                int gx  = x0 - SR + 4 * k;
                bool ok = ((unsigned)gy < (unsigned)H_TOTAL) &&
                          ((unsigned)gx <= (unsigned)(W_TOTAL - 4));
                src[i] = ok ? (wb + (size_t)c * plane + (size_t)gy * W_TOTAL + gx) : wb;
                dst[i] = base_w + (uint32_t)(((c * HH + r) * WPAD + 4 * k) * 4);
                sz[i]  = ok ? 16 : 0;
                bufoff[i] = sizeof(s_w) / 2;
            } else {
                src[i] = wb; dst[i] = base_w; sz[i] = -1; bufoff[i] = 0;
            }
        }
    }
    const size_t CHSTEP = (size_t)CC * plane;

    // ---- accumulators ----
    // acc_e[k][0]: (px0,px1) dx=2k      acc_e[k][1]: (px2,px3) dx=2k
    // acc_c[k][0]: lo->(px1,dx=2k-1), hi->(px0,dx=2k+1)
    // acc_c[k][1]: lo->(px3,dx=2k-1), hi->(px2,dx=2k+1)
    unsigned long long acc_e[5][2], acc_c[5][2];
    #pragma unroll
    for (int k = 0; k < 5; k++) {
        acc_e[k][0] = 0ull; acc_e[k][1] = 0ull;
        acc_c[k][0] = 0ull; acc_c[k][1] = 0ull;
    }

    // ---- prologue ----
    #pragma unroll
    for (int i = 0; i < 3; i++)
        if (sz[i] >= 0) CP16(dst[i], src[i], sz[i]);
    CP_COMMIT();

    #pragma unroll 1
    for (int ch = 0; ch < NCHUNK; ch++) {
        const int cur = ch & 1;
        if (ch + 1 < NCHUNK) {
            const size_t   goff = (size_t)(ch + 1) * CHSTEP;
            const uint32_t nb   = (ch + 1) & 1;
            #pragma unroll
            for (int i = 0; i < 3; i++)
                if (sz[i] >= 0) CP16(dst[i] + nb * bufoff[i], src[i] + goff, sz[i]);
            CP_COMMIT();
            CP_WAIT(1);
        } else {
            CP_WAIT(0);
        }
        __syncthreads();

        #pragma unroll
        for (int c = 0; c < CC; c++) {
            const ulonglong2 avv = *(const ulonglong2*)&s_c1[cur][c][row][tx0];
            const ulonglong2* wr = (const ulonglong2*)&s_w[cur][c][row + dy][tx0];
            const ulonglong2 wv0 = wr[0];
            const ulonglong2 wv1 = wr[1];
            const ulonglong2 wv2 = wr[2];
            const unsigned long long P[6] = {wv0.x, wv0.y, wv1.x, wv1.y, wv2.x, wv2.y};

            float a0, a1, a2, a3;
            UNPACK2(a0, a1, avv.x);
            UNPACK2(a2, a3, avv.y);
            unsigned long long rev01, rev23;
            PACK2(rev01, a1, a0);
            PACK2(rev23, a3, a2);

            #pragma unroll
            for (int k = 0; k < 5; k++) {
                FMA2(acc_e[k][0], avv.x, P[k]);
                FMA2(acc_e[k][1], avv.y, P[k + 1]);
                FMA2(acc_c[k][0], rev01, P[k]);
                FMA2(acc_c[k][1], rev23, P[k + 1]);
            }
        }
        __syncthreads();
    }

    // ---- epilogue: route, mean, leaky-relu, ST.128 ----
    const float inv = 1.0f / (float)C_TOTAL;
    float* ob = out + (size_t)b * 81 * plane + (size_t)(dy * 9) * plane
                    + (size_t)(y0 + row) * W_TOTAL + (x0 + tx0);

    float ce_lo[5][2], ce_hi[5][2], cc_lo[5][2], cc_hi[5][2];
    #pragma unroll
    for (int k = 0; k < 5; k++) {
        UNPACK2(ce_lo[k][0], ce_hi[k][0], acc_e[k][0]);
        UNPACK2(ce_lo[k][1], ce_hi[k][1], acc_e[k][1]);
        UNPACK2(cc_lo[k][0], cc_hi[k][0], acc_c[k][0]);
        UNPACK2(cc_lo[k][1], cc_hi[k][1], acc_c[k][1]);
    }

    #pragma unroll
    for (int dx = 0; dx < 9; dx++) {
        float r0, r1, r2, r3;
        if ((dx & 1) == 0) {
            int k = dx >> 1;
            r0 = ce_lo[k][0]; r1 = ce_hi[k][0];
            r2 = ce_lo[k][1]; r3 = ce_hi[k][1];
        } else {
            int k = dx >> 1;              // dx = 2k+1
            r0 = cc_hi[k][0];             // px0 dx=2k+1
            r1 = cc_lo[k + 1][0];         // px1 dx=2(k+1)-1
            r2 = cc_hi[k][1];
            r3 = cc_lo[k + 1][1];
        }
        r0 *= inv; r1 *= inv; r2 *= inv; r3 *= inv;
        float4 v;
        v.x = (r0 >= 0.f) ? r0 : av * r0;
        v.y = (r1 >= 0.f) ? r1 : av * r1;
        v.z = (r2 >= 0.f) ? r2 : av * r2;
        v.w = (r3 >= 0.f) ? r3 : av * r3;
        *(float4*)(ob + (size_t)dx * plane) = v;
    }
}

extern "C" void kernel_launch(void* const* d_in, const int* in_sizes, int n_in,
                              void* d_out, int out_size) {
    const float* c1     = (const float*)d_in[0];
    const float* warped = (const float*)d_in[1];
    const float* alpha  = (const float*)d_in[2];
    float* out          = (float*)d_out;

    cudaFuncSetAttribute(costvol_kernel,
                         cudaFuncAttributePreferredSharedMemoryCarveout, 100);

    dim3 grid(W_TOTAL / TW, H_TOTAL / TH, B_TOTAL);   // (5, 32, 8) = 1280
    dim3 block(NTHREADS);
    costvol_kernel<<<grid, block>>>(c1, warped, alpha, out);
}